// round 16
// baseline (speedup 1.0000x reference)
#include <cuda_runtime.h>
#include <cuda_fp16.h>
#include <math_constants.h>
#include <cstdint>

#define DIM 2048
#define N_HEADS 16
#define N_KV_HEADS 4
#define HEAD_DIM 128
#define BB 2
#define SS 2048
#define ROWS (BB*SS)                  // 4096
#define KV_DIM (N_KV_HEADS*HEAD_DIM)  // 512
#define NQKV (DIM + 2*KV_DIM)         // 3072

// Q is pre-scaled by softmax_scale * log2(e) so attention uses ex2 directly.
#define QSC 0.1275174329366458f       // (1/sqrt(128)) * log2(e)

// ---------------- static scratch (no allocations allowed) ----------------
__device__ __half g_xh  [(size_t)ROWS * DIM];
__device__ __half g_wqkv[(size_t)DIM * NQKV];
__device__ __half g_woh [(size_t)DIM * DIM];
__device__ __half g_Qh  [(size_t)ROWS * DIM];
__device__ __half g_Kh  [(size_t)ROWS * KV_DIM];
__device__ __half g_Vh  [(size_t)ROWS * KV_DIM];
__device__ __half g_Oh  [(size_t)ROWS * DIM];

// ---------------- low-level helpers ----------------
__device__ __forceinline__ uint32_t sptr(const void* p) {
    return (uint32_t)__cvta_generic_to_shared(p);
}
__device__ __forceinline__ void cp16(uint32_t dst, const void* src) {
    asm volatile("cp.async.cg.shared.global [%0], [%1], 16;\n" :: "r"(dst), "l"(src));
}
#define CP_COMMIT asm volatile("cp.async.commit_group;\n" ::: "memory")
#define CP_WAIT(N) asm volatile("cp.async.wait_group %0;\n" :: "n"(N) : "memory")

__device__ __forceinline__ void ldsm_x4(uint32_t* r, uint32_t a) {
    asm volatile("ldmatrix.sync.aligned.m8n8.x4.shared.b16 {%0,%1,%2,%3}, [%4];"
                 : "=r"(r[0]), "=r"(r[1]), "=r"(r[2]), "=r"(r[3]) : "r"(a));
}
__device__ __forceinline__ void ldsm_x4t(uint32_t* r, uint32_t a) {
    asm volatile("ldmatrix.sync.aligned.m8n8.x4.trans.shared.b16 {%0,%1,%2,%3}, [%4];"
                 : "=r"(r[0]), "=r"(r[1]), "=r"(r[2]), "=r"(r[3]) : "r"(a));
}
__device__ __forceinline__ void mma_f16(float* d, const uint32_t* a, uint32_t b0, uint32_t b1) {
    asm volatile(
        "mma.sync.aligned.m16n8k16.row.col.f32.f16.f16.f32 "
        "{%0,%1,%2,%3}, {%4,%5,%6,%7}, {%8,%9}, {%0,%1,%2,%3};"
        : "+f"(d[0]), "+f"(d[1]), "+f"(d[2]), "+f"(d[3])
        : "r"(a[0]), "r"(a[1]), "r"(a[2]), "r"(a[3]), "r"(b0), "r"(b1));
}
// bit-reinterpret: pack two floats -> half2 -> u32
__device__ __forceinline__ uint32_t pack_h2(float lo, float hi) {
    __half2 h = __floats2half2_rn(lo, hi);
    return *reinterpret_cast<uint32_t*>(&h);
}
// raw MUFU.EX2 (handles -inf -> 0)
__device__ __forceinline__ float ex2f(float x) {
    float r;
    asm("ex2.approx.ftz.f32 %0, %1;" : "=f"(r) : "f"(x));
    return r;
}

// ---------------- fp32 -> fp16 convert ----------------
__global__ void f2h(const float* __restrict__ in, __half* __restrict__ out, int n2) {
    int i = blockIdx.x * blockDim.x + threadIdx.x;
    if (i < n2) {
        float2 v = ((const float2*)in)[i];
        ((__half2*)out)[i] = __floats2half2_rn(v.x, v.y);
    }
}

// ---------------- concat wq|wk|wv -> fp16 [DIM][3072] ----------------
__global__ void wcat(const float* __restrict__ wq, const float* __restrict__ wk,
                     const float* __restrict__ wv, __half* __restrict__ out, int total2)
{
    int i = blockIdx.x * blockDim.x + threadIdx.x;
    if (i >= total2) return;
    int j = i * 2;
    int k = j / NQKV, n = j % NQKV;
    float2 v;
    if (n < DIM)                 v = *(const float2*)&wq[(size_t)k * DIM + n];
    else if (n < DIM + KV_DIM)   v = *(const float2*)&wk[(size_t)k * KV_DIM + (n - DIM)];
    else                         v = *(const float2*)&wv[(size_t)k * KV_DIM + (n - DIM - KV_DIM)];
    ((__half2*)out)[i] = __floats2half2_rn(v.x, v.y);
}

// ---------------- fp16 GEMM: 128x128x32, 6-stage ring, 2 stages/barrier --
// 128 thr (4 warps 64x64), 2 CTA/SM. One CP_WAIT+__syncthreads per TWO
// k-iters (wait_group 2 guarantees the two oldest stages are resident).
// EPI: 0 = fp32 C, 2 = fused QKV split + RoPE (+QSC folded into Q).
template<int EPI>
__global__ __launch_bounds__(128, 2) void hgemm(
    const __half* __restrict__ A, const __half* __restrict__ B,
    float* __restrict__ C,
    __half* __restrict__ qout, __half* __restrict__ kout, __half* __restrict__ vout,
    const float* __restrict__ cosb, const float* __restrict__ sinb,
    int M, int N, int K)
{
    constexpr int BM = 128, BN = 128, BK = 32, STG = 6;
    constexpr int ASTR = BK + 8;           // 40 halves
    constexpr int BSTR = BN + 8;           // 136 halves
    constexpr int ASZB = BM * ASTR * 2;    // 10240
    constexpr int BSZB = BK * BSTR * 2;    // 8704
    constexpr int NNI  = 8;                // 64/8

    extern __shared__ char smem[];
    const uint32_t sA = sptr(smem);
    const uint32_t sB = sA + STG * ASZB;

    const int tid = threadIdx.x, warp = tid >> 5, lane = tid & 31;
    const int g = lane >> 2, c = lane & 3;
    const int wm = (warp & 1) * 64, wn = (warp >> 1) * 64;
    const int bm = blockIdx.y * BM, bn = blockIdx.x * BN;

    auto issue = [&](int kt) {
        const int st = kt % STG;
        const uint32_t da = sA + st * ASZB;
        const __half* ga = A + (size_t)bm * K + (size_t)kt * BK;
        #pragma unroll
        for (int i = tid; i < 128 * 4; i += 128) {
            int r = i >> 2, ch = i & 3;
            cp16(da + (r * ASTR + ch * 8) * 2, ga + (size_t)r * K + ch * 8);
        }
        const uint32_t db = sB + st * BSZB;
        const __half* gb = B + (size_t)kt * BK * N + bn;
        #pragma unroll
        for (int i = tid; i < 32 * 16; i += 128) {
            int r = i >> 4, ch = i & 15;
            cp16(db + (r * BSTR + ch * 8) * 2, gb + (size_t)r * N + ch * 8);
        }
    };

    issue(0); CP_COMMIT;
    issue(1); CP_COMMIT;
    issue(2); CP_COMMIT;
    issue(3); CP_COMMIT;

    float acc[4][NNI][4];
    #pragma unroll
    for (int mi = 0; mi < 4; mi++)
        #pragma unroll
        for (int ni = 0; ni < NNI; ni++)
            #pragma unroll
            for (int r = 0; r < 4; r++) acc[mi][ni][r] = 0.f;

    const uint32_t aBase = sA + (((wm + (lane & 15)) * ASTR) + ((lane >> 4) << 3)) * 2;
    const uint32_t bBase = sB + (((((lane >> 3) & 1) * 8 + (lane & 7)) * BSTR)
                                 + wn + ((lane >> 4) << 3)) * 2;

    // one stage worth of fragment-batched mma work
    auto process = [&](int st) {
        const uint32_t ab = aBase + st * ASZB;
        const uint32_t bb = bBase + st * BSZB;
        uint32_t af[2][4][4];
        uint32_t bf[2][NNI][2];
        #pragma unroll
        for (int kk = 0; kk < 2; kk++) {
            const int kb = kk * 16;
            #pragma unroll
            for (int mi = 0; mi < 4; mi++)
                ldsm_x4(af[kk][mi], ab + (mi * 16 * ASTR + kb) * 2);
            #pragma unroll
            for (int nip = 0; nip < NNI / 2; nip++) {
                uint32_t t[4];
                ldsm_x4t(t, bb + (kb * BSTR + nip * 16) * 2);
                bf[kk][2 * nip][0] = t[0]; bf[kk][2 * nip][1] = t[1];
                bf[kk][2 * nip + 1][0] = t[2]; bf[kk][2 * nip + 1][1] = t[3];
            }
        }
        #pragma unroll
        for (int kk = 0; kk < 2; kk++)
            #pragma unroll
            for (int mi = 0; mi < 4; mi++)
                #pragma unroll
                for (int ni = 0; ni < NNI; ni++)
                    mma_f16(acc[mi][ni], af[kk][mi], bf[kk][ni][0], bf[kk][ni][1]);
    };

    const int NT = K / BK;                 // even (K multiple of 64)
    for (int kt = 0; kt < NT; kt += 2) {
        CP_WAIT(2);                        // stages kt, kt+1 resident
        __syncthreads();
        if (kt + 4 < NT) { issue(kt + 4); CP_COMMIT; }
        if (kt + 5 < NT) { issue(kt + 5); CP_COMMIT; }
        process(kt % STG);
        process((kt + 1) % STG);
    }

    // ---- epilogue ----
    #pragma unroll
    for (int mi = 0; mi < 4; mi++) {
        const int r0 = bm + wm + mi * 16 + g;
        const int r1 = r0 + 8;
        #pragma unroll
        for (int ni = 0; ni < NNI; ni++) {
            const int col = bn + wn + ni * 8 + 2 * c;
            float v0 = acc[mi][ni][0], v1 = acc[mi][ni][1];
            float v2 = acc[mi][ni][2], v3 = acc[mi][ni][3];
            if (EPI == 0) {
                *(float2*)&C[(size_t)r0 * N + col] = make_float2(v0, v1);
                *(float2*)&C[(size_t)r1 * N + col] = make_float2(v2, v3);
            } else {
                const int s0 = r0 & (SS - 1), s1 = r1 & (SS - 1);
                if (col < DIM) {                      // Q + RoPE, pre-scaled by QSC
                    const int d2 = (col & 127) >> 1;
                    float c0 = cosb[s0 * 64 + d2], n0 = sinb[s0 * 64 + d2];
                    float c1 = cosb[s1 * 64 + d2], n1 = sinb[s1 * 64 + d2];
                    *(__half2*)&qout[(size_t)r0 * DIM + col] =
                        __floats2half2_rn((v0 * c0 - v1 * n0) * QSC, (v0 * n0 + v1 * c0) * QSC);
                    *(__half2*)&qout[(size_t)r1 * DIM + col] =
                        __floats2half2_rn((v2 * c1 - v3 * n1) * QSC, (v2 * n1 + v3 * c1) * QSC);
                } else if (col < DIM + KV_DIM) {      // K + RoPE
                    const int cc = col - DIM;
                    const int d2 = (cc & 127) >> 1;
                    float c0 = cosb[s0 * 64 + d2], n0 = sinb[s0 * 64 + d2];
                    float c1 = cosb[s1 * 64 + d2], n1 = sinb[s1 * 64 + d2];
                    *(__half2*)&kout[(size_t)r0 * KV_DIM + cc] =
                        __floats2half2_rn(v0 * c0 - v1 * n0, v0 * n0 + v1 * c0);
                    *(__half2*)&kout[(size_t)r1 * KV_DIM + cc] =
                        __floats2half2_rn(v2 * c1 - v3 * n1, v2 * n1 + v3 * c1);
                } else {                              // V
                    const int cc = col - DIM - KV_DIM;
                    *(__half2*)&vout[(size_t)r0 * KV_DIM + cc] = __floats2half2_rn(v0, v1);
                    *(__half2*)&vout[(size_t)r1 * KV_DIM + cc] = __floats2half2_rn(v2, v3);
                }
            }
        }
    }
}

// ---------------- FlashAttention fp16: KT=64, 2-stage cp.async K/V -------
// (R15 config, unchanged)
#define KT   64
#define QSTR 136
#define KSTR 136
#define VSTR 136
#define KSTGB (KT*KSTR*2)
#define VSTGB (KT*VSTR*2)
#define ATTN_SMEM ((128*QSTR + 2*KT*KSTR + 2*KT*VSTR) * 2)

__global__ __launch_bounds__(256, 2) void flash_attn(
    const __half* __restrict__ Qg, const __half* __restrict__ Kg,
    const __half* __restrict__ Vg, __half* __restrict__ Og)
{
    extern __shared__ char smem[];
    __half* shQ = (__half*)smem;
    __half* shK = shQ + 128 * QSTR;
    __half* shV = shK + 2 * KT * KSTR;
    const uint32_t sQ = sptr(shQ), sK = sptr(shK), sV = sptr(shV);

    const int qt = gridDim.x - 1 - blockIdx.x;   // heavy blocks first
    const int h = blockIdx.y, b = blockIdx.z;
    const int kh = h >> 2;
    const int tid = threadIdx.x;
    const int warp = tid >> 5, lane = tid & 31;
    const int g = lane >> 2, c = lane & 3;
    const int wrow = warp * 16;

    const int nkt = (qt + 1) * 2;                // 64-key tiles

    {
        const __half* gq = Qg + ((size_t)(b * SS + qt * 128) * N_HEADS + h) * HEAD_DIM;
        #pragma unroll
        for (int i = tid; i < 128 * 16; i += 256) {
            int r = i >> 4, ch = i & 15;
            cp16(sQ + (r * QSTR + ch * 8) * 2, gq + (size_t)r * N_HEADS * HEAD_DIM + ch * 8);
        }
    }
    auto kv_issue = [&](int s) {
        const int buf = s & 1;
        const __half* gk = Kg + ((size_t)(b * SS + s * KT) * N_KV_HEADS + kh) * HEAD_DIM;
        const __half* gv = Vg + ((size_t)(b * SS + s * KT) * N_KV_HEADS + kh) * HEAD_DIM;
        #pragma unroll
        for (int i = tid; i < KT * 16; i += 256) {
            int r = i >> 4, ch = i & 15;
            size_t off = (size_t)r * N_KV_HEADS * HEAD_DIM + ch * 8;
            cp16(sK + buf * KSTGB + (r * KSTR + ch * 8) * 2, gk + off);
            cp16(sV + buf * VSTGB + (r * VSTR + ch * 8) * 2, gv + off);
        }
    };
    kv_issue(0); CP_COMMIT;
    if (nkt > 1) kv_issue(1);
    CP_COMMIT;

    float o[16][4];
    #pragma unroll
    for (int nt = 0; nt < 16; nt++)
        #pragma unroll
        for (int r = 0; r < 4; r++) o[nt][r] = 0.f;

    float m0 = -CUDART_INF_F, m1 = -CUDART_INF_F, l0 = 0.f, l1 = 0.f;
    const int r0g = qt * 128 + wrow + g;
    const int r1g = r0g + 8;

    const uint32_t qB = sQ + (((wrow + (lane & 15)) * QSTR) + ((lane >> 4) << 3)) * 2;
    const uint32_t kB0 = sK + (((((lane >> 4) << 3) + (lane & 7)) * KSTR)
                               + (((lane >> 3) & 1) << 3)) * 2;
    const uint32_t vB0 = sV + ((((((lane >> 3) & 1) << 3) + (lane & 7)) * VSTR)
                               + ((lane >> 4) << 3)) * 2;

    for (int jt = 0; jt < nkt; jt++) {
        CP_WAIT(1);
        __syncthreads();

        const int buf = jt & 1, t0 = jt * KT;
        const uint32_t kB = kB0 + buf * KSTGB;
        const uint32_t vB = vB0 + buf * VSTGB;

        // ---- S = Q K^T : 16 x 64 per warp (Q already scaled) ----
        float s4[8][4];
        #pragma unroll
        for (int ni = 0; ni < 8; ni++)
            #pragma unroll
            for (int r = 0; r < 4; r++) s4[ni][r] = 0.f;

        #pragma unroll
        for (int ks = 0; ks < 8; ks++) {
            const int kb = ks * 16;
            uint32_t qf[4];
            ldsm_x4(qf, qB + kb * 2);
            #pragma unroll
            for (int n16 = 0; n16 < 4; n16++) {
                uint32_t kf[4];
                ldsm_x4(kf, kB + (n16 * 16 * KSTR + kb) * 2);
                mma_f16(s4[2 * n16],     qf, kf[0], kf[1]);
                mma_f16(s4[2 * n16 + 1], qf, kf[2], kf[3]);
            }
        }

        if (jt >= nkt - 2) {   // diagonal blocks
            #pragma unroll
            for (int ni = 0; ni < 8; ni++) {
                int key0 = t0 + ni * 8 + 2 * c;
                if (key0 > r0g)     s4[ni][0] = -CUDART_INF_F;
                if (key0 + 1 > r0g) s4[ni][1] = -CUDART_INF_F;
                if (key0 > r1g)     s4[ni][2] = -CUDART_INF_F;
                if (key0 + 1 > r1g) s4[ni][3] = -CUDART_INF_F;
            }
        }

        // ---- online softmax over 64 keys (one pass) ----
        float mx0 = -CUDART_INF_F, mx1 = -CUDART_INF_F;
        #pragma unroll
        for (int ni = 0; ni < 8; ni++) {
            mx0 = fmaxf(mx0, fmaxf(s4[ni][0], s4[ni][1]));
            mx1 = fmaxf(mx1, fmaxf(s4[ni][2], s4[ni][3]));
        }
        mx0 = fmaxf(mx0, __shfl_xor_sync(0xffffffffu, mx0, 1));
        mx0 = fmaxf(mx0, __shfl_xor_sync(0xffffffffu, mx0, 2));
        mx1 = fmaxf(mx1, __shfl_xor_sync(0xffffffffu, mx1, 1));
        mx1 = fmaxf(mx1, __shfl_xor_sync(0xffffffffu, mx1, 2));

        float mn0 = fmaxf(m0, mx0), mn1 = fmaxf(m1, mx1);
        float corr0 = ex2f(m0 - mn0), corr1 = ex2f(m1 - mn1);
        m0 = mn0; m1 = mn1;

        if (__any_sync(0xffffffffu, (corr0 != 1.f) | (corr1 != 1.f))) {
            #pragma unroll
            for (int nt = 0; nt < 16; nt++) {
                o[nt][0] *= corr0; o[nt][1] *= corr0;
                o[nt][2] *= corr1; o[nt][3] *= corr1;
            }
        }
        l0 *= corr0;
        l1 *= corr1;

        // ---- exp2 + PV in two 32-key halves (bounds register pressure) ----
        #pragma unroll
        for (int half = 0; half < 2; half++) {
            uint32_t pr[4][2];
            float ps0 = 0.f, ps1 = 0.f;
            #pragma unroll
            for (int ni = 0; ni < 4; ni++) {
                float p0 = ex2f(s4[half * 4 + ni][0] - mn0);
                float p1 = ex2f(s4[half * 4 + ni][1] - mn0);
                float p2 = ex2f(s4[half * 4 + ni][2] - mn1);
                float p3 = ex2f(s4[half * 4 + ni][3] - mn1);
                ps0 += p0 + p1;
                ps1 += p2 + p3;
                pr[ni][0] = pack_h2(p0, p1);
                pr[ni][1] = pack_h2(p2, p3);
            }
            l0 += ps0;
            l1 += ps1;
            #pragma unroll
            for (int ks = 0; ks < 2; ks++) {
                uint32_t pf[4] = { pr[2 * ks][0], pr[2 * ks][1],
                                   pr[2 * ks + 1][0], pr[2 * ks + 1][1] };
                const int kb = half * 32 + ks * 16;
                #pragma unroll
                for (int np = 0; np < 8; np++) {
                    uint32_t vf[4];
                    ldsm_x4t(vf, vB + (kb * VSTR + np * 16) * 2);
                    mma_f16(o[2 * np],     pf, vf[0], vf[1]);
                    mma_f16(o[2 * np + 1], pf, vf[2], vf[3]);
                }
            }
        }

        // all warps done with this buffer before re-issuing into it
        __syncthreads();
        if (jt + 2 < nkt) kv_issue(jt + 2);
        CP_COMMIT;
    }

    // final l reduction across the quad (deferred from the loop)
    l0 += __shfl_xor_sync(0xffffffffu, l0, 1);
    l0 += __shfl_xor_sync(0xffffffffu, l0, 2);
    l1 += __shfl_xor_sync(0xffffffffu, l1, 1);
    l1 += __shfl_xor_sync(0xffffffffu, l1, 2);

    const float inv0 = 1.f / l0, inv1 = 1.f / l1;
    #pragma unroll
    for (int nt = 0; nt < 16; nt++) {
        int col = h * HEAD_DIM + nt * 8 + 2 * c;
        *(__half2*)&Og[(size_t)(b * SS + r0g) * DIM + col] =
            __floats2half2_rn(o[nt][0] * inv0, o[nt][1] * inv0);
        *(__half2*)&Og[(size_t)(b * SS + r1g) * DIM + col] =
            __floats2half2_rn(o[nt][2] * inv1, o[nt][3] * inv1);
    }
}

// ---------------- launch ----------------
extern "C" void kernel_launch(void* const* d_in, const int* in_sizes, int n_in,
                              void* d_out, int out_size)
{
    const float* x    = (const float*)d_in[0];
    const float* fcos = (const float*)d_in[1];
    const float* fsin = (const float*)d_in[2];
    const float* wq   = (const float*)d_in[3];
    const float* wk   = (const float*)d_in[4];
    const float* wv   = (const float*)d_in[5];
    const float* wo   = (const float*)d_in[6];
    float* out = (float*)d_out;

    __half *xh, *wqkvh, *woh, *Qh, *Kh, *Vh, *Oh;
    cudaGetSymbolAddress((void**)&xh,    g_xh);
    cudaGetSymbolAddress((void**)&wqkvh, g_wqkv);
    cudaGetSymbolAddress((void**)&woh,   g_woh);
    cudaGetSymbolAddress((void**)&Qh,    g_Qh);
    cudaGetSymbolAddress((void**)&Kh,    g_Kh);
    cudaGetSymbolAddress((void**)&Vh,    g_Vh);
    cudaGetSymbolAddress((void**)&Oh,    g_Oh);

    // ---- conversions ----
    {
        int n = ROWS * DIM / 2;
        f2h<<<(n + 255) / 256, 256>>>(x, xh, n);
        int n2 = DIM * NQKV / 2;
        wcat<<<(n2 + 255) / 256, 256>>>(wq, wk, wv, wqkvh, n2);
        int n3 = DIM * DIM / 2;
        f2h<<<(n3 + 255) / 256, 256>>>(wo, woh, n3);
    }

    const int smem_gemm = 6 * (128 * 40 * 2 + 32 * 136 * 2);   // 113,664
    cudaFuncSetAttribute((const void*)hgemm<2>,
                         cudaFuncAttributeMaxDynamicSharedMemorySize, smem_gemm);
    cudaFuncSetAttribute((const void*)hgemm<0>,
                         cudaFuncAttributeMaxDynamicSharedMemorySize, smem_gemm);
    cudaFuncSetAttribute((const void*)flash_attn,
                         cudaFuncAttributeMaxDynamicSharedMemorySize, ATTN_SMEM);

    // ---- fused QKV projection + RoPE (+QSC on Q) + fp16 store ----
    hgemm<2><<<dim3(NQKV / 128, ROWS / 128), 128, smem_gemm>>>(
        xh, wqkvh, nullptr, Qh, Kh, Vh, fcos, fsin, ROWS, NQKV, DIM);

    // ---- attention ----
    flash_attn<<<dim3(SS / 128, N_HEADS, BB), 256, ATTN_SMEM>>>(Qh, Kh, Vh, Oh);

    // ---- output projection (fp32 out) ----
    hgemm<0><<<dim3(DIM / 128, ROWS / 128), 128, smem_gemm>>>(
        Oh, woh, out, nullptr, nullptr, nullptr, nullptr, nullptr, ROWS, DIM, DIM);
}

// round 17
// speedup vs baseline: 1.1137x; 1.1137x over previous
#include <cuda_runtime.h>
#include <cuda_fp16.h>
#include <math_constants.h>
#include <cstdint>

#define DIM 2048
#define N_HEADS 16
#define N_KV_HEADS 4
#define HEAD_DIM 128
#define BB 2
#define SS 2048
#define ROWS (BB*SS)                  // 4096
#define KV_DIM (N_KV_HEADS*HEAD_DIM)  // 512
#define NQKV (DIM + 2*KV_DIM)         // 3072

// Q is pre-scaled by softmax_scale * log2(e) so attention uses ex2 directly.
#define QSC 0.1275174329366458f       // (1/sqrt(128)) * log2(e)

// ---------------- static scratch (no allocations allowed) ----------------
__device__ __half g_xh  [(size_t)ROWS * DIM];
__device__ __half g_wqkv[(size_t)DIM * NQKV];
__device__ __half g_woh [(size_t)DIM * DIM];
__device__ __half g_Qh  [(size_t)ROWS * DIM];
__device__ __half g_Kh  [(size_t)ROWS * KV_DIM];
__device__ __half g_Vh  [(size_t)ROWS * KV_DIM];
__device__ __half g_Oh  [(size_t)ROWS * DIM];

// ---------------- low-level helpers ----------------
__device__ __forceinline__ uint32_t sptr(const void* p) {
    return (uint32_t)__cvta_generic_to_shared(p);
}
__device__ __forceinline__ void cp16(uint32_t dst, const void* src) {
    asm volatile("cp.async.cg.shared.global [%0], [%1], 16;\n" :: "r"(dst), "l"(src));
}
#define CP_COMMIT asm volatile("cp.async.commit_group;\n" ::: "memory")
#define CP_WAIT(N) asm volatile("cp.async.wait_group %0;\n" :: "n"(N) : "memory")

__device__ __forceinline__ void ldsm_x4(uint32_t* r, uint32_t a) {
    asm volatile("ldmatrix.sync.aligned.m8n8.x4.shared.b16 {%0,%1,%2,%3}, [%4];"
                 : "=r"(r[0]), "=r"(r[1]), "=r"(r[2]), "=r"(r[3]) : "r"(a));
}
__device__ __forceinline__ void ldsm_x4t(uint32_t* r, uint32_t a) {
    asm volatile("ldmatrix.sync.aligned.m8n8.x4.trans.shared.b16 {%0,%1,%2,%3}, [%4];"
                 : "=r"(r[0]), "=r"(r[1]), "=r"(r[2]), "=r"(r[3]) : "r"(a));
}
__device__ __forceinline__ void mma_f16(float* d, const uint32_t* a, uint32_t b0, uint32_t b1) {
    asm volatile(
        "mma.sync.aligned.m16n8k16.row.col.f32.f16.f16.f32 "
        "{%0,%1,%2,%3}, {%4,%5,%6,%7}, {%8,%9}, {%0,%1,%2,%3};"
        : "+f"(d[0]), "+f"(d[1]), "+f"(d[2]), "+f"(d[3])
        : "r"(a[0]), "r"(a[1]), "r"(a[2]), "r"(a[3]), "r"(b0), "r"(b1));
}
// bit-reinterpret: pack two floats -> half2 -> u32
__device__ __forceinline__ uint32_t pack_h2(float lo, float hi) {
    __half2 h = __floats2half2_rn(lo, hi);
    return *reinterpret_cast<uint32_t*>(&h);
}
// raw MUFU.EX2 (handles -inf -> 0)
__device__ __forceinline__ float ex2f(float x) {
    float r;
    asm("ex2.approx.ftz.f32 %0, %1;" : "=f"(r) : "f"(x));
    return r;
}

// ---------------- fused conversions: x->fp16, wq|wk|wv->concat, wo->fp16 --
#define NX2 (ROWS*DIM/2)          // 4,194,304 half2
#define NW2 (DIM*NQKV/2)          // 3,145,728
#define NO2 (DIM*DIM/2)           // 2,097,152
#define NCVT (NX2+NW2+NO2)

__global__ void convert_all(const float* __restrict__ x,
                            const float* __restrict__ wq, const float* __restrict__ wk,
                            const float* __restrict__ wv, const float* __restrict__ wo,
                            __half* __restrict__ xh, __half* __restrict__ wqkvh,
                            __half* __restrict__ woh)
{
    int i = blockIdx.x * blockDim.x + threadIdx.x;
    if (i < NX2) {
        float2 v = ((const float2*)x)[i];
        ((__half2*)xh)[i] = __floats2half2_rn(v.x, v.y);
    } else if (i < NX2 + NW2) {
        int t = i - NX2;
        int j = t * 2;
        int k = j / NQKV, n = j % NQKV;
        float2 v;
        if (n < DIM)                 v = *(const float2*)&wq[(size_t)k * DIM + n];
        else if (n < DIM + KV_DIM)   v = *(const float2*)&wk[(size_t)k * KV_DIM + (n - DIM)];
        else                         v = *(const float2*)&wv[(size_t)k * KV_DIM + (n - DIM - KV_DIM)];
        ((__half2*)wqkvh)[t] = __floats2half2_rn(v.x, v.y);
    } else if (i < NCVT) {
        int t = i - NX2 - NW2;
        float2 v = ((const float2*)wo)[t];
        ((__half2*)woh)[t] = __floats2half2_rn(v.x, v.y);
    }
}

// ---------------- fp16 GEMM (R13 config): 128x128x32, 4-stage, 128 thr ---
// 2 CTA/SM, warp tile 64x64, fragments batched per k-iter.
// EPI: 0 = fp32 C, 2 = fused QKV split + RoPE (+QSC folded into Q).
template<int EPI>
__global__ __launch_bounds__(128, 2) void hgemm(
    const __half* __restrict__ A, const __half* __restrict__ B,
    float* __restrict__ C,
    __half* __restrict__ qout, __half* __restrict__ kout, __half* __restrict__ vout,
    const float* __restrict__ cosb, const float* __restrict__ sinb,
    int M, int N, int K)
{
    constexpr int BM = 128, BN = 128, BK = 32, STG = 4;
    constexpr int ASTR = BK + 8;           // 40 halves
    constexpr int BSTR = BN + 8;           // 136 halves
    constexpr int ASZB = BM * ASTR * 2;    // 10240
    constexpr int BSZB = BK * BSTR * 2;    // 8704
    constexpr int NNI  = 8;                // 64/8

    extern __shared__ char smem[];
    const uint32_t sA = sptr(smem);
    const uint32_t sB = sA + STG * ASZB;

    const int tid = threadIdx.x, warp = tid >> 5, lane = tid & 31;
    const int g = lane >> 2, c = lane & 3;
    const int wm = (warp & 1) * 64, wn = (warp >> 1) * 64;
    const int bm = blockIdx.y * BM, bn = blockIdx.x * BN;

    auto issue = [&](int kt) {
        const int st = kt & (STG - 1);
        const uint32_t da = sA + st * ASZB;
        const __half* ga = A + (size_t)bm * K + (size_t)kt * BK;
        #pragma unroll
        for (int i = tid; i < 128 * 4; i += 128) {
            int r = i >> 2, ch = i & 3;
            cp16(da + (r * ASTR + ch * 8) * 2, ga + (size_t)r * K + ch * 8);
        }
        const uint32_t db = sB + st * BSZB;
        const __half* gb = B + (size_t)kt * BK * N + bn;
        #pragma unroll
        for (int i = tid; i < 32 * 16; i += 128) {
            int r = i >> 4, ch = i & 15;
            cp16(db + (r * BSTR + ch * 8) * 2, gb + (size_t)r * N + ch * 8);
        }
    };

    issue(0); CP_COMMIT;
    issue(1); CP_COMMIT;
    issue(2); CP_COMMIT;

    float acc[4][NNI][4];
    #pragma unroll
    for (int mi = 0; mi < 4; mi++)
        #pragma unroll
        for (int ni = 0; ni < NNI; ni++)
            #pragma unroll
            for (int r = 0; r < 4; r++) acc[mi][ni][r] = 0.f;

    const uint32_t aBase = sA + (((wm + (lane & 15)) * ASTR) + ((lane >> 4) << 3)) * 2;
    const uint32_t bBase = sB + (((((lane >> 3) & 1) * 8 + (lane & 7)) * BSTR)
                                 + wn + ((lane >> 4) << 3)) * 2;

    const int NT = K / BK;
    for (int kt = 0; kt < NT; kt++) {
        CP_WAIT(2);
        __syncthreads();
        if (kt + 3 < NT) issue(kt + 3);
        CP_COMMIT;

        const int st = kt & (STG - 1);
        const uint32_t ab = aBase + st * ASZB;
        const uint32_t bb = bBase + st * BSZB;

        uint32_t af[2][4][4];
        uint32_t bf[2][NNI][2];
        #pragma unroll
        for (int kk = 0; kk < 2; kk++) {
            const int kb = kk * 16;
            #pragma unroll
            for (int mi = 0; mi < 4; mi++)
                ldsm_x4(af[kk][mi], ab + (mi * 16 * ASTR + kb) * 2);
            #pragma unroll
            for (int nip = 0; nip < NNI / 2; nip++) {
                uint32_t t[4];
                ldsm_x4t(t, bb + (kb * BSTR + nip * 16) * 2);
                bf[kk][2 * nip][0] = t[0]; bf[kk][2 * nip][1] = t[1];
                bf[kk][2 * nip + 1][0] = t[2]; bf[kk][2 * nip + 1][1] = t[3];
            }
        }
        #pragma unroll
        for (int kk = 0; kk < 2; kk++)
            #pragma unroll
            for (int mi = 0; mi < 4; mi++)
                #pragma unroll
                for (int ni = 0; ni < NNI; ni++)
                    mma_f16(acc[mi][ni], af[kk][mi], bf[kk][ni][0], bf[kk][ni][1]);
    }

    // ---- epilogue ----
    #pragma unroll
    for (int mi = 0; mi < 4; mi++) {
        const int r0 = bm + wm + mi * 16 + g;
        const int r1 = r0 + 8;
        #pragma unroll
        for (int ni = 0; ni < NNI; ni++) {
            const int col = bn + wn + ni * 8 + 2 * c;
            float v0 = acc[mi][ni][0], v1 = acc[mi][ni][1];
            float v2 = acc[mi][ni][2], v3 = acc[mi][ni][3];
            if (EPI == 0) {
                *(float2*)&C[(size_t)r0 * N + col] = make_float2(v0, v1);
                *(float2*)&C[(size_t)r1 * N + col] = make_float2(v2, v3);
            } else {
                const int s0 = r0 & (SS - 1), s1 = r1 & (SS - 1);
                if (col < DIM) {                      // Q + RoPE, pre-scaled by QSC
                    const int d2 = (col & 127) >> 1;
                    float c0 = cosb[s0 * 64 + d2], n0 = sinb[s0 * 64 + d2];
                    float c1 = cosb[s1 * 64 + d2], n1 = sinb[s1 * 64 + d2];
                    *(__half2*)&qout[(size_t)r0 * DIM + col] =
                        __floats2half2_rn((v0 * c0 - v1 * n0) * QSC, (v0 * n0 + v1 * c0) * QSC);
                    *(__half2*)&qout[(size_t)r1 * DIM + col] =
                        __floats2half2_rn((v2 * c1 - v3 * n1) * QSC, (v2 * n1 + v3 * c1) * QSC);
                } else if (col < DIM + KV_DIM) {      // K + RoPE
                    const int cc = col - DIM;
                    const int d2 = (cc & 127) >> 1;
                    float c0 = cosb[s0 * 64 + d2], n0 = sinb[s0 * 64 + d2];
                    float c1 = cosb[s1 * 64 + d2], n1 = sinb[s1 * 64 + d2];
                    *(__half2*)&kout[(size_t)r0 * KV_DIM + cc] =
                        __floats2half2_rn(v0 * c0 - v1 * n0, v0 * n0 + v1 * c0);
                    *(__half2*)&kout[(size_t)r1 * KV_DIM + cc] =
                        __floats2half2_rn(v2 * c1 - v3 * n1, v2 * n1 + v3 * c1);
                } else {                              // V
                    const int cc = col - DIM - KV_DIM;
                    *(__half2*)&vout[(size_t)r0 * KV_DIM + cc] = __floats2half2_rn(v0, v1);
                    *(__half2*)&vout[(size_t)r1 * KV_DIM + cc] = __floats2half2_rn(v2, v3);
                }
            }
        }
    }
}

// ---------------- FlashAttention fp16: KT=64, 2-stage cp.async K/V -------
// R15 config + fully-masked warp-tiles skip all compute (barriers intact).
#define KT   64
#define QSTR 136
#define KSTR 136
#define VSTR 136
#define KSTGB (KT*KSTR*2)
#define VSTGB (KT*VSTR*2)
#define ATTN_SMEM ((128*QSTR + 2*KT*KSTR + 2*KT*VSTR) * 2)

__global__ __launch_bounds__(256, 2) void flash_attn(
    const __half* __restrict__ Qg, const __half* __restrict__ Kg,
    const __half* __restrict__ Vg, __half* __restrict__ Og)
{
    extern __shared__ char smem[];
    __half* shQ = (__half*)smem;
    __half* shK = shQ + 128 * QSTR;
    __half* shV = shK + 2 * KT * KSTR;
    const uint32_t sQ = sptr(shQ), sK = sptr(shK), sV = sptr(shV);

    const int qt = gridDim.x - 1 - blockIdx.x;   // heavy blocks first
    const int h = blockIdx.y, b = blockIdx.z;
    const int kh = h >> 2;
    const int tid = threadIdx.x;
    const int warp = tid >> 5, lane = tid & 31;
    const int g = lane >> 2, c = lane & 3;
    const int wrow = warp * 16;

    const int nkt = (qt + 1) * 2;                // 64-key tiles

    {
        const __half* gq = Qg + ((size_t)(b * SS + qt * 128) * N_HEADS + h) * HEAD_DIM;
        #pragma unroll
        for (int i = tid; i < 128 * 16; i += 256) {
            int r = i >> 4, ch = i & 15;
            cp16(sQ + (r * QSTR + ch * 8) * 2, gq + (size_t)r * N_HEADS * HEAD_DIM + ch * 8);
        }
    }
    auto kv_issue = [&](int s) {
        const int buf = s & 1;
        const __half* gk = Kg + ((size_t)(b * SS + s * KT) * N_KV_HEADS + kh) * HEAD_DIM;
        const __half* gv = Vg + ((size_t)(b * SS + s * KT) * N_KV_HEADS + kh) * HEAD_DIM;
        #pragma unroll
        for (int i = tid; i < KT * 16; i += 256) {
            int r = i >> 4, ch = i & 15;
            size_t off = (size_t)r * N_KV_HEADS * HEAD_DIM + ch * 8;
            cp16(sK + buf * KSTGB + (r * KSTR + ch * 8) * 2, gk + off);
            cp16(sV + buf * VSTGB + (r * VSTR + ch * 8) * 2, gv + off);
        }
    };
    kv_issue(0); CP_COMMIT;
    if (nkt > 1) kv_issue(1);
    CP_COMMIT;

    float o[16][4];
    #pragma unroll
    for (int nt = 0; nt < 16; nt++)
        #pragma unroll
        for (int r = 0; r < 4; r++) o[nt][r] = 0.f;

    float m0 = -CUDART_INF_F, m1 = -CUDART_INF_F, l0 = 0.f, l1 = 0.f;
    const int r0g = qt * 128 + wrow + g;
    const int r1g = r0g + 8;
    const int rowmax = qt * 128 + wrow + 15;     // last q-row this warp owns

    const uint32_t qB = sQ + (((wrow + (lane & 15)) * QSTR) + ((lane >> 4) << 3)) * 2;
    const uint32_t kB0 = sK + (((((lane >> 4) << 3) + (lane & 7)) * KSTR)
                               + (((lane >> 3) & 1) << 3)) * 2;
    const uint32_t vB0 = sV + ((((((lane >> 3) & 1) << 3) + (lane & 7)) * VSTR)
                               + ((lane >> 4) << 3)) * 2;

    for (int jt = 0; jt < nkt; jt++) {
        CP_WAIT(1);
        __syncthreads();

        const int buf = jt & 1, t0 = jt * KT;

        if (t0 <= rowmax) {   // warp has at least one unmasked key in this tile
            const uint32_t kB = kB0 + buf * KSTGB;
            const uint32_t vB = vB0 + buf * VSTGB;

            // ---- S = Q K^T : 16 x 64 per warp (Q already scaled) ----
            float s4[8][4];
            #pragma unroll
            for (int ni = 0; ni < 8; ni++)
                #pragma unroll
                for (int r = 0; r < 4; r++) s4[ni][r] = 0.f;

            #pragma unroll
            for (int ks = 0; ks < 8; ks++) {
                const int kb = ks * 16;
                uint32_t qf[4];
                ldsm_x4(qf, qB + kb * 2);
                #pragma unroll
                for (int n16 = 0; n16 < 4; n16++) {
                    uint32_t kf[4];
                    ldsm_x4(kf, kB + (n16 * 16 * KSTR + kb) * 2);
                    mma_f16(s4[2 * n16],     qf, kf[0], kf[1]);
                    mma_f16(s4[2 * n16 + 1], qf, kf[2], kf[3]);
                }
            }

            if (jt >= nkt - 2) {   // diagonal blocks
                #pragma unroll
                for (int ni = 0; ni < 8; ni++) {
                    int key0 = t0 + ni * 8 + 2 * c;
                    if (key0 > r0g)     s4[ni][0] = -CUDART_INF_F;
                    if (key0 + 1 > r0g) s4[ni][1] = -CUDART_INF_F;
                    if (key0 > r1g)     s4[ni][2] = -CUDART_INF_F;
                    if (key0 + 1 > r1g) s4[ni][3] = -CUDART_INF_F;
                }
            }

            // ---- online softmax over 64 keys (one pass) ----
            float mx0 = -CUDART_INF_F, mx1 = -CUDART_INF_F;
            #pragma unroll
            for (int ni = 0; ni < 8; ni++) {
                mx0 = fmaxf(mx0, fmaxf(s4[ni][0], s4[ni][1]));
                mx1 = fmaxf(mx1, fmaxf(s4[ni][2], s4[ni][3]));
            }
            mx0 = fmaxf(mx0, __shfl_xor_sync(0xffffffffu, mx0, 1));
            mx0 = fmaxf(mx0, __shfl_xor_sync(0xffffffffu, mx0, 2));
            mx1 = fmaxf(mx1, __shfl_xor_sync(0xffffffffu, mx1, 1));
            mx1 = fmaxf(mx1, __shfl_xor_sync(0xffffffffu, mx1, 2));

            float mn0 = fmaxf(m0, mx0), mn1 = fmaxf(m1, mx1);
            float corr0 = ex2f(m0 - mn0), corr1 = ex2f(m1 - mn1);
            m0 = mn0; m1 = mn1;

            if (__any_sync(0xffffffffu, (corr0 != 1.f) | (corr1 != 1.f))) {
                #pragma unroll
                for (int nt = 0; nt < 16; nt++) {
                    o[nt][0] *= corr0; o[nt][1] *= corr0;
                    o[nt][2] *= corr1; o[nt][3] *= corr1;
                }
            }
            l0 *= corr0;
            l1 *= corr1;

            // ---- exp2 + PV in two 32-key halves ----
            #pragma unroll
            for (int half = 0; half < 2; half++) {
                uint32_t pr[4][2];
                float ps0 = 0.f, ps1 = 0.f;
                #pragma unroll
                for (int ni = 0; ni < 4; ni++) {
                    float p0 = ex2f(s4[half * 4 + ni][0] - mn0);
                    float p1 = ex2f(s4[half * 4 + ni][1] - mn0);
                    float p2 = ex2f(s4[half * 4 + ni][2] - mn1);
                    float p3 = ex2f(s4[half * 4 + ni][3] - mn1);
                    ps0 += p0 + p1;
                    ps1 += p2 + p3;
                    pr[ni][0] = pack_h2(p0, p1);
                    pr[ni][1] = pack_h2(p2, p3);
                }
                l0 += ps0;
                l1 += ps1;
                #pragma unroll
                for (int ks = 0; ks < 2; ks++) {
                    uint32_t pf[4] = { pr[2 * ks][0], pr[2 * ks][1],
                                       pr[2 * ks + 1][0], pr[2 * ks + 1][1] };
                    const int kb = half * 32 + ks * 16;
                    #pragma unroll
                    for (int np = 0; np < 8; np++) {
                        uint32_t vf[4];
                        ldsm_x4t(vf, vB + (kb * VSTR + np * 16) * 2);
                        mma_f16(o[2 * np],     pf, vf[0], vf[1]);
                        mma_f16(o[2 * np + 1], pf, vf[2], vf[3]);
                    }
                }
            }
        }

        // all warps done with this buffer before re-issuing into it
        __syncthreads();
        if (jt + 2 < nkt) kv_issue(jt + 2);
        CP_COMMIT;
    }

    // final l reduction across the quad (deferred from the loop)
    l0 += __shfl_xor_sync(0xffffffffu, l0, 1);
    l0 += __shfl_xor_sync(0xffffffffu, l0, 2);
    l1 += __shfl_xor_sync(0xffffffffu, l1, 1);
    l1 += __shfl_xor_sync(0xffffffffu, l1, 2);

    const float inv0 = 1.f / l0, inv1 = 1.f / l1;
    #pragma unroll
    for (int nt = 0; nt < 16; nt++) {
        int col = h * HEAD_DIM + nt * 8 + 2 * c;
        *(__half2*)&Og[(size_t)(b * SS + r0g) * DIM + col] =
            __floats2half2_rn(o[nt][0] * inv0, o[nt][1] * inv0);
        *(__half2*)&Og[(size_t)(b * SS + r1g) * DIM + col] =
            __floats2half2_rn(o[nt][2] * inv1, o[nt][3] * inv1);
    }
}

// ---------------- launch ----------------
extern "C" void kernel_launch(void* const* d_in, const int* in_sizes, int n_in,
                              void* d_out, int out_size)
{
    const float* x    = (const float*)d_in[0];
    const float* fcos = (const float*)d_in[1];
    const float* fsin = (const float*)d_in[2];
    const float* wq   = (const float*)d_in[3];
    const float* wk   = (const float*)d_in[4];
    const float* wv   = (const float*)d_in[5];
    const float* wo   = (const float*)d_in[6];
    float* out = (float*)d_out;

    __half *xh, *wqkvh, *woh, *Qh, *Kh, *Vh, *Oh;
    cudaGetSymbolAddress((void**)&xh,    g_xh);
    cudaGetSymbolAddress((void**)&wqkvh, g_wqkv);
    cudaGetSymbolAddress((void**)&woh,   g_woh);
    cudaGetSymbolAddress((void**)&Qh,    g_Qh);
    cudaGetSymbolAddress((void**)&Kh,    g_Kh);
    cudaGetSymbolAddress((void**)&Vh,    g_Vh);
    cudaGetSymbolAddress((void**)&Oh,    g_Oh);

    // ---- fused conversions (one launch) ----
    convert_all<<<(NCVT + 255) / 256, 256>>>(x, wq, wk, wv, wo, xh, wqkvh, woh);

    const int smem_gemm = 4 * (128 * 40 * 2 + 32 * 136 * 2);   // 75,776
    cudaFuncSetAttribute((const void*)hgemm<2>,
                         cudaFuncAttributeMaxDynamicSharedMemorySize, smem_gemm);
    cudaFuncSetAttribute((const void*)hgemm<0>,
                         cudaFuncAttributeMaxDynamicSharedMemorySize, smem_gemm);
    cudaFuncSetAttribute((const void*)flash_attn,
                         cudaFuncAttributeMaxDynamicSharedMemorySize, ATTN_SMEM);

    // ---- fused QKV projection + RoPE (+QSC on Q) + fp16 store ----
    hgemm<2><<<dim3(NQKV / 128, ROWS / 128), 128, smem_gemm>>>(
        xh, wqkvh, nullptr, Qh, Kh, Vh, fcos, fsin, ROWS, NQKV, DIM);

    // ---- attention ----
    flash_attn<<<dim3(SS / 128, N_HEADS, BB), 256, ATTN_SMEM>>>(Qh, Kh, Vh, Oh);

    // ---- output projection (fp32 out) ----
    hgemm<0><<<dim3(DIM / 128, ROWS / 128), 128, smem_gemm>>>(
        Oh, woh, out, nullptr, nullptr, nullptr, nullptr, nullptr, ROWS, DIM, DIM);
}